// round 11
// baseline (speedup 1.0000x reference)
#include <cuda_runtime.h>
#include <math_constants.h>

#define BATCH 8
#define HH 224
#define WW 224
#define OH 223
#define OW 223
#define NBLK 49          // 7x7 blocks per batch
#define NPIX (33 * 33)   // 1089 halo pixels
#define PI_F 3.14159265358979323846f

// Per-(batch,block) min/max partials — block-owned slots, written every launch.
__device__ float g_pmin[BATCH][NBLK];
__device__ float g_pmax[BATCH][NBLK];
// Monotonic ticket counter per batch (never reset; wrap-safe signed compare).
__device__ unsigned g_cnt[BATCH];

static __device__ __forceinline__ unsigned ldcg_u32(const unsigned* p) {
    unsigned v;
    asm volatile("ld.global.cg.u32 %0, [%1];" : "=r"(v) : "l"(p) : "memory");
    return v;
}

__global__ void __launch_bounds__(256)
quanv_fused(const float* __restrict__ x, const float* __restrict__ wts,
            float* __restrict__ out) {
    __shared__ float2 sTS[NPIX];        // {t = cos(a)cos(b), s = sin(a)}
    __shared__ float sred[16];          // 8 warp mins + 8 warp maxs
    __shared__ float s_rm[2][2];        // [min|max][warp]
    __shared__ float s_cw[4], s_sw[4];

    const int b   = blockIdx.z;
    const int blk = blockIdx.y * 7 + blockIdx.x;   // 0..48
    const int tid = threadIdx.x;
    const int r0  = blockIdx.y * 32;
    const int c0  = blockIdx.x * 32;

    if (tid < 4) {
        float w = wts[tid];
        s_cw[tid] = cosf(w);
        s_sw[tid] = sinf(w);
    }

    const float* x0 = x + (size_t)b * 2 * HH * WW;
    const float* x1 = x0 + HH * WW;

    // ---- Single read phase: halo -> registers, min/max on the fly.
    // The 49 halos' union covers the full 224x224 (clamped duplicates are
    // harmless for min/max), so no separate batch-slice read is needed.
    float ra[5], rb[5];
    float lmin = CUDART_INF_F, lmax = -CUDART_INF_F;
    #pragma unroll
    for (int j = 0; j < 5; j++) {
        int i = tid + j * 256;
        if (i < NPIX) {
            int rr = i / 33, cc = i - rr * 33;
            int r = min(r0 + rr, HH - 1);
            int c = min(c0 + cc, WW - 1);
            float va = __ldg(x0 + r * WW + c);
            float vb = __ldg(x1 + r * WW + c);
            ra[j] = va; rb[j] = vb;
            lmin = fminf(lmin, fminf(va, vb));
            lmax = fmaxf(lmax, fmaxf(va, vb));
        }
    }
    #pragma unroll
    for (int off = 16; off > 0; off >>= 1) {
        lmin = fminf(lmin, __shfl_xor_sync(0xFFFFFFFFu, lmin, off));
        lmax = fmaxf(lmax, __shfl_xor_sync(0xFFFFFFFFu, lmax, off));
    }
    if ((tid & 31) == 0) { sred[tid >> 5] = lmin; sred[8 + (tid >> 5)] = lmax; }
    __syncthreads();

    // ---- Publish partial + arrive (atomic ticket), wait via plain L2 loads ----
    if (tid == 0) {
        float m0 = sred[0], m1 = sred[8];
        #pragma unroll
        for (int i = 1; i < 8; i++) {
            m0 = fminf(m0, sred[i]);
            m1 = fmaxf(m1, sred[8 + i]);
        }
        __stcg(&g_pmin[b][blk], m0);
        __stcg(&g_pmax[b][blk], m1);
        __threadfence();                               // partials visible before arrive
        unsigned ticket = atomicAdd(&g_cnt[b], 1u);
        unsigned target = ticket - (ticket % NBLK) + NBLK;
        while ((int)(ldcg_u32(&g_cnt[b]) - target) < 0) { }
        __threadfence();                               // acquire
    }
    __syncthreads();

    // ---- Reduce the 49 partials (two warps; BOTH min and max per warp,
    //      then cross-warp combine — this is the R10 bug fix) ----
    if (tid < 64) {
        float pm = CUDART_INF_F, px = -CUDART_INF_F;
        if (tid < NBLK) {
            pm = __ldcg(&g_pmin[b][tid]);
            px = __ldcg(&g_pmax[b][tid]);
        }
        #pragma unroll
        for (int off = 16; off > 0; off >>= 1) {
            pm = fminf(pm, __shfl_xor_sync(0xFFFFFFFFu, pm, off));
            px = fmaxf(px, __shfl_xor_sync(0xFFFFFFFFu, px, off));
        }
        if ((tid & 31) == 0) {
            s_rm[0][tid >> 5] = pm;
            s_rm[1][tid >> 5] = px;
        }
    }
    __syncthreads();

    const float fmn = fminf(s_rm[0][0], s_rm[0][1]);
    const float fmx = fmaxf(s_rm[1][0], s_rm[1][1]);
    const float scale = PI_F / (fmx - fmn + 1e-8f);

    // ---- Transform registers -> packed smem ----
    #pragma unroll
    for (int j = 0; j < 5; j++) {
        int i = tid + j * 256;
        if (i < NPIX) {
            float a  = (ra[j] - fmn) * scale;
            float bb = (rb[j] - fmn) * scale;
            float sa, ca;
            __sincosf(a, &sa, &ca);
            sTS[i] = make_float2(ca * __cosf(bb), sa);
        }
    }
    __syncthreads();

    // ---- Output: z_i = cw_i*t - sw_i*s at 4 corners, parity products ----
    const float cw0 = s_cw[0], sw0 = s_sw[0];
    const float cw1 = s_cw[1], sw1 = s_sw[1];
    const float cw2 = s_cw[2], sw2 = s_sw[2];
    const float cw3 = s_cw[3], sw3 = s_sw[3];

    const int tx = tid & 31;
    const int ty = tid >> 5;
    const size_t plane = (size_t)OH * OW;
    float* ob = out + (size_t)b * 4 * plane;

    #pragma unroll
    for (int k = 0; k < 4; k++) {
        int ly = ty * 4 + k;
        int oh = r0 + ly;
        int ow = c0 + tx;
        if (oh < OH && ow < OW) {
            int p = ly * 33 + tx;
            float2 v0 = sTS[p];
            float2 v1 = sTS[p + 1];
            float2 v2 = sTS[p + 33];
            float2 v3 = sTS[p + 34];
            float z0 = fmaf(cw0, v0.x, -sw0 * v0.y);
            float z1 = fmaf(cw1, v1.x, -sw1 * v1.y);
            float z2 = fmaf(cw2, v2.x, -sw2 * v2.y);
            float z3 = fmaf(cw3, v3.x, -sw3 * v3.y);
            float z01 = z0 * z1;
            float z23 = z2 * z3;
            size_t o = (size_t)oh * OW + ow;
            ob[0 * plane + o] = z1 * z23;   // <Z0> = z1 z2 z3
            ob[1 * plane + o] = z01;        // <Z1> = z0 z1
            ob[2 * plane + o] = z01 * z2;   // <Z2> = z0 z1 z2
            ob[3 * plane + o] = z01 * z23;  // <Z3> = z0 z1 z2 z3
        }
    }
}

extern "C" void kernel_launch(void* const* d_in, const int* in_sizes, int n_in,
                              void* d_out, int out_size) {
    const float* x   = (const float*)d_in[0];   // [8,2,224,224]
    const float* wts = (const float*)d_in[1];   // [1,4]
    float* out = (float*)d_out;                 // [8,4,223,223]

    dim3 grid(7, 7, BATCH);                     // 392 blocks, all co-resident
    quanv_fused<<<grid, 256>>>(x, wts, out);
}